// round 6
// baseline (speedup 1.0000x reference)
#include <cuda_runtime.h>
#include <cuda_bf16.h>
#include <cstdint>

#define BB   32
#define NN   2048
#define HH   64
#define OUTD 128
#define KK   16

// ---------------- scratch (static device globals; no runtime allocation) ----
__device__ float g_buf0[BB * NN * HH];
__device__ float g_buf1[BB * NN * HH];
__device__ float g_A[BB * NN * HH];
__device__ float g_C[BB * NN * HH];
__device__ int   g_nbr[BB * NN * KK];
__device__ __align__(16) __nv_bfloat16 g_xhi[BB * NN * HH];
__device__ __align__(16) __nv_bfloat16 g_xlo[BB * NN * HH];
__device__ float g_sq[BB * NN];

// ---------------- fp32 -> (bf16 hi, bf16 lo) split + squared norms ----------
template <int D, int DP>
__global__ __launch_bounds__(128) void convert_kernel(
    const float* __restrict__ X, __nv_bfloat16* __restrict__ Hh,
    __nv_bfloat16* __restrict__ Ll, float* __restrict__ SQ) {
    const int node = blockIdx.x * 128 + threadIdx.x;
    const float* xp = X + (size_t)node * D;
    float s = 0.f;
#pragma unroll
    for (int d = 0; d < DP; d++) {
        float v = (d < D) ? xp[d] : 0.f;
        s = fmaf(v, v, s);
        __nv_bfloat16 h = __float2bfloat16(v);
        float r = v - __bfloat162float(h);
        Hh[(size_t)node * DP + d] = h;
        Ll[(size_t)node * DP + d] = __float2bfloat16(r);
    }
    SQ[node] = s;
}

// ---------------- asm helpers ------------------------------------------------
__device__ __forceinline__ void mma_bf16(float* c, const uint32_t* a,
                                         uint32_t b0, uint32_t b1) {
    asm volatile(
        "mma.sync.aligned.m16n8k16.row.col.f32.bf16.bf16.f32 "
        "{%0,%1,%2,%3},{%4,%5,%6,%7},{%8,%9},{%0,%1,%2,%3};"
        : "+f"(c[0]), "+f"(c[1]), "+f"(c[2]), "+f"(c[3])
        : "r"(a[0]), "r"(a[1]), "r"(a[2]), "r"(a[3]), "r"(b0), "r"(b1));
}
__device__ __forceinline__ void ldsm4(uint32_t* r, uint32_t addr) {
    asm volatile("ldmatrix.sync.aligned.m8n8.x4.shared.b16 {%0,%1,%2,%3}, [%4];"
                 : "=r"(r[0]), "=r"(r[1]), "=r"(r[2]), "=r"(r[3]) : "r"(addr));
}
#define CPA16(d, s) asm volatile("cp.async.ca.shared.global [%0], [%1], 16;" :: "r"(d), "l"(s) : "memory")
#define CPCOMMIT()  asm volatile("cp.async.commit_group;" ::: "memory")
#define CPWAIT()    asm volatile("cp.async.wait_group 0;" ::: "memory")

// ---------------- tensor-core kNN (4 CTA/SM: swizzled planes, lean buffers) -
// 64 queries/block, 64-candidate tiles, ldmatrix frags, cp.async overlap with
// selection, buffered selection with warp-synchronized flushes.
// DP=64: XOR-swizzled 128B rows (no padding).  DP=16: padded rows.
template <int DP>
__global__ __launch_bounds__(128, 4) void knn_mma_kernel(
    const __nv_bfloat16* __restrict__ Xh, const __nv_bfloat16* __restrict__ Xl,
    const float* __restrict__ SQ, int* __restrict__ nbr) {
    constexpr int NK = DP / 16;
    constexpr int CS = 68;                 // key row stride (floats)
    constexpr int NT = NN / 64;            // 32 tiles
    constexpr int CH = DP / 8;             // 16B chunks per row
    constexpr bool SWZ = (DP == 64);
    constexpr int PB = SWZ ? 64 * 128 : 64 * (DP + 8) * 2;  // bytes per plane
    constexpr int OKEY = 4 * PB;
    constexpr int OSQC = OKEY + 64 * CS * 4;
    constexpr int OBUF = OSQC + 256;
    constexpr int BD = 6;                  // selection buffer depth

    extern __shared__ __align__(16) char SB[];
    char* sQh = SB;
    char* sQl = SB + PB;
    char* sCh = SB + 2 * PB;
    char* sCl = SB + 3 * PB;
    float* sKey = (float*)(SB + OKEY);
    float* sSqc = (float*)(SB + OSQC);
    uint2* sBuf = (uint2*)(SB + OBUF);

    const int b = blockIdx.y;
    const int qbase = blockIdx.x * 64;
    const int tid = threadIdx.x;
    const int lane = tid & 31;
    const int warp = tid >> 5;

    // byte offset of 16B chunk c4 in row r (within one plane)
    auto rowoff = [&](int r, int c4) -> uint32_t {
        if (SWZ) return (uint32_t)(r * 128 + ((c4 ^ (r & 7)) << 4));
        else     return (uint32_t)(r * (DP + 8) * 2 + (c4 << 4));
    };

    // ---- load Q tile (once) ----
    {
        const uint4* gh = (const uint4*)(Xh + ((size_t)b * NN + qbase) * DP);
        const uint4* gl = (const uint4*)(Xl + ((size_t)b * NN + qbase) * DP);
        for (int u = tid; u < 64 * CH; u += 128) {
            int r = u / CH, c = u % CH;
            uint32_t off = rowoff(r, c);
            *(uint4*)(sQh + off) = gh[u];
            *(uint4*)(sQl + off) = gl[u];
        }
    }

    const uint32_t sQh_s = (uint32_t)__cvta_generic_to_shared(sQh);
    const uint32_t sQl_s = (uint32_t)__cvta_generic_to_shared(sQl);
    const uint32_t sCh_s = (uint32_t)__cvta_generic_to_shared(sCh);
    const uint32_t sCl_s = (uint32_t)__cvta_generic_to_shared(sCl);

    const int lrow = (lane & 7) + ((lane >> 3) & 1) * 8;
    const int lchunk = (lane >> 4) & 1;  // 16B chunk within k-step

    // ---- selection state ----
    float bd[16];
    int bi[16];
#pragma unroll
    for (int t = 0; t < 16; t++) { bd[t] = 3.4028235e38f; bi[t] = 0; }
    float thr = 3.4028235e38f;
    int cnt = 0;
    const int selq = tid & 63;
    const int half = tid >> 6;

    auto loadC = [&](int ct) {
        const uint4* gh = (const uint4*)(Xh + ((size_t)b * NN + ct * 64) * DP);
        const uint4* gl = (const uint4*)(Xl + ((size_t)b * NN + ct * 64) * DP);
#pragma unroll
        for (int u = tid; u < 64 * CH; u += 128) {
            int r = u / CH, c = u % CH;
            uint32_t off = rowoff(r, c);
            CPA16(sCh_s + off, gh + u);
            CPA16(sCl_s + off, gl + u);
        }
        if (tid < 64) sSqc[tid] = SQ[b * NN + ct * 64 + tid];
        CPCOMMIT();
    };

    auto mma_tile = [&]() {
        float acc[8][4];
#pragma unroll
        for (int i = 0; i < 8; i++)
#pragma unroll
            for (int j = 0; j < 4; j++) acc[i][j] = 0.f;

#pragma unroll
        for (int ks = 0; ks < NK; ks++) {
            const int c4 = ks * 2 + lchunk;
            uint32_t ah[4], al[4];
            ldsm4(ah, sQh_s + rowoff(warp * 16 + lrow, c4));
            ldsm4(al, sQl_s + rowoff(warp * 16 + lrow, c4));
#pragma unroll
            for (int cp = 0; cp < 4; cp++) {
                uint32_t bh[4], bl[4];
                ldsm4(bh, sCh_s + rowoff(cp * 16 + lrow, c4));
                ldsm4(bl, sCl_s + rowoff(cp * 16 + lrow, c4));
                mma_bf16(acc[2 * cp], ah, bh[0], bh[2]);
                mma_bf16(acc[2 * cp], ah, bl[0], bl[2]);
                mma_bf16(acc[2 * cp], al, bh[0], bh[2]);
                mma_bf16(acc[2 * cp + 1], ah, bh[1], bh[3]);
                mma_bf16(acc[2 * cp + 1], ah, bl[1], bl[3]);
                mma_bf16(acc[2 * cp + 1], al, bh[1], bh[3]);
            }
        }
        const int r0 = warp * 16 + (lane >> 2);
#pragma unroll
        for (int nt = 0; nt < 8; nt++) {
            const int n0 = nt * 8 + (lane & 3) * 2;
            float2 sq2 = *(const float2*)(sSqc + n0);
            *(float2*)(sKey + r0 * CS + n0) =
                make_float2(sq2.x - 2.f * acc[nt][0], sq2.y - 2.f * acc[nt][1]);
            *(float2*)(sKey + (r0 + 8) * CS + n0) =
                make_float2(sq2.x - 2.f * acc[nt][2], sq2.y - 2.f * acc[nt][3]);
        }
    };

    auto flush = [&]() {
        int n = cnt;
        cnt = 0;
#pragma unroll 1
        for (int i = 0; i < n; i++) {
            uint2 u = sBuf[tid * BD + i];
            float k = __uint_as_float(u.x);
            int id = (int)u.y;
            if (k < bd[15]) {
                bd[15] = k; bi[15] = id;
#pragma unroll
                for (int t = 15; t > 0; t--) {
                    if (bd[t] < bd[t - 1]) {
                        float td = bd[t]; bd[t] = bd[t - 1]; bd[t - 1] = td;
                        int ti = bi[t]; bi[t] = bi[t - 1]; bi[t - 1] = ti;
                    }
                }
            }
        }
        thr = bd[15];
    };

    auto select = [&](int ct) {
        const float* kp = sKey + selq * CS + half * 32;
        const int base = ct * 64 + half * 32;
#pragma unroll 1
        for (int g = 0; g < 8; g++) {
            if (__any_sync(0xffffffffu, cnt >= 3)) flush();
            float4 v = *(const float4*)(kp + g * 4);
            const int ib = base + g * 4;
            if (v.x < thr) { sBuf[tid * BD + cnt] = make_uint2(__float_as_uint(v.x), ib); cnt++; }
            if (v.y < thr) { sBuf[tid * BD + cnt] = make_uint2(__float_as_uint(v.y), ib + 1); cnt++; }
            if (v.z < thr) { sBuf[tid * BD + cnt] = make_uint2(__float_as_uint(v.z), ib + 2); cnt++; }
            if (v.w < thr) { sBuf[tid * BD + cnt] = make_uint2(__float_as_uint(v.w), ib + 3); cnt++; }
        }
    };

    // ---- pipeline ----
    loadC(0);
    CPWAIT();
    __syncthreads();
    mma_tile();
#pragma unroll 1
    for (int ct = 1; ct < NT; ct++) {
        __syncthreads();
        loadC(ct);
        select(ct - 1);
        CPWAIT();
        __syncthreads();
        mma_tile();
    }
    __syncthreads();
    select(NT - 1);
    flush();
    __syncthreads();

    // ---- merge two halves (stable, index tie-break) ----
    float* mD = sKey;                          // 64*33 floats
    int* mI = (int*)((char*)sKey + 64 * 33 * 4);  // extends into sSqc/sBuf (dead now)
    {
        const int base = selq * 33 + half * 16;
#pragma unroll
        for (int t = 0; t < 16; t++) { mD[base + t] = bd[t]; mI[base + t] = bi[t]; }
    }
    __syncthreads();
    if (tid < 64) {
        const float* dA = mD + tid * 33;
        const int* iA = mI + tid * 33;
        int ia = 0, ib2 = 16;
        int* o = nbr + ((size_t)b * NN + qbase + tid) * KK;
#pragma unroll
        for (int r = 0; r < 16; r++) {
            float da = dA[ia], db = dA[ib2];
            int xa = iA[ia], xb = iA[ib2];
            bool ta = (da < db) || (da == db && xa < xb);
            o[r] = ta ? xa : xb;
            if (ta) ia++; else ib2++;
        }
    }
}

// ---------------- precompute: register-tiled (4 nodes x 4 h per thread) -----
template <int D>
__global__ __launch_bounds__(256) void precompute_kernel(
    const float* __restrict__ X, const float* __restrict__ w1,
    const float* __restrict__ b1, float* __restrict__ A, float* __restrict__ C) {
    extern __shared__ float PS[];
    float* swd = PS;              // D*64
    float* swb = PS + D * 64;     // D*64
    float* sxt = PS + 2 * D * 64; // D*64 transposed: sxt[d*64 + n]

    const int base = blockIdx.x * 64;
    for (int t = threadIdx.x; t < D * HH; t += 256) {
        float bot = w1[D * HH + t];
        swd[t] = w1[t] - bot;
        swb[t] = bot;
    }
    for (int t = threadIdx.x; t < 64 * D; t += 256) {
        int n = t / D, d = t % D;
        sxt[d * 64 + n] = X[(size_t)base * D + t];
    }
    __syncthreads();

    const int hq = threadIdx.x & 15;
    const int nq = threadIdx.x >> 4;
    const int h0 = hq * 4;
    const float4 bias = *(const float4*)(b1 + h0);

    float a[4][4], c[4][4];
#pragma unroll
    for (int i = 0; i < 4; i++) {
        a[i][0] = bias.x; a[i][1] = bias.y; a[i][2] = bias.z; a[i][3] = bias.w;
        c[i][0] = c[i][1] = c[i][2] = c[i][3] = 0.f;
    }

#pragma unroll
    for (int d = 0; d < D; d++) {
        float4 wd4 = *(const float4*)(swd + d * 64 + h0);
        float4 wb4 = *(const float4*)(swb + d * 64 + h0);
        float4 x4 = *(const float4*)(sxt + d * 64 + nq * 4);
        const float xv[4] = {x4.x, x4.y, x4.z, x4.w};
#pragma unroll
        for (int i = 0; i < 4; i++) {
            a[i][0] = fmaf(xv[i], wd4.x, a[i][0]);
            a[i][1] = fmaf(xv[i], wd4.y, a[i][1]);
            a[i][2] = fmaf(xv[i], wd4.z, a[i][2]);
            a[i][3] = fmaf(xv[i], wd4.w, a[i][3]);
            c[i][0] = fmaf(xv[i], wb4.x, c[i][0]);
            c[i][1] = fmaf(xv[i], wb4.y, c[i][1]);
            c[i][2] = fmaf(xv[i], wb4.z, c[i][2]);
            c[i][3] = fmaf(xv[i], wb4.w, c[i][3]);
        }
    }
#pragma unroll
    for (int i = 0; i < 4; i++) {
        const size_t row = (size_t)(base + nq * 4 + i) * HH + h0;
        *(float4*)(A + row) = make_float4(a[i][0], a[i][1], a[i][2], a[i][3]);
        *(float4*)(C + row) = make_float4(c[i][0], c[i][1], c[i][2], c[i][3]);
    }
}

// ---------------- edge aggregate + output GEMM (64 nodes/block) -------------
__global__ __launch_bounds__(256) void edge_agg_kernel(
    const int* __restrict__ nbr, const float* __restrict__ A,
    const float* __restrict__ C, const float* __restrict__ wo,
    const float* __restrict__ bo, float* __restrict__ out) {
    __shared__ float swo[HH * HH];
    __shared__ float S[64 * 68];
    __shared__ int snbr[64 * KK];

    const int base = blockIdx.x * 64;
    for (int t = threadIdx.x; t < HH * HH; t += 256) swo[t] = wo[t];
    for (int t = threadIdx.x; t < 64 * KK; t += 256) snbr[t] = nbr[(size_t)base * KK + t];
    __syncthreads();

    const int hq = threadIdx.x & 15;
    const int nq = threadIdx.x >> 4;
    const int h0 = hq * 4;
    const int bofs = ((base >> 11) << 11);
    const float* Cb = C + (size_t)bofs * HH;

#pragma unroll
    for (int i = 0; i < 4; i++) {
        const int n = nq * 4 + i;
        float4 a4 = *(const float4*)(A + (size_t)(base + n) * HH + h0);
        float sx = 0.f, sy = 0.f, sz = 0.f, sw = 0.f;
#pragma unroll
        for (int k = 0; k < KK; k++) {
            int j = snbr[n * KK + k];
            float4 c4 = *(const float4*)(Cb + (size_t)j * HH + h0);
            sx += fmaxf(a4.x + c4.x, 0.f);
            sy += fmaxf(a4.y + c4.y, 0.f);
            sz += fmaxf(a4.z + c4.z, 0.f);
            sw += fmaxf(a4.w + c4.w, 0.f);
        }
        *(float4*)(S + n * 68 + h0) =
            make_float4(sx * (1.f / KK), sy * (1.f / KK), sz * (1.f / KK), sw * (1.f / KK));
    }
    __syncthreads();

    const float4 b4 = *(const float4*)(bo + h0);
    float o[4][4];
#pragma unroll
    for (int i = 0; i < 4; i++) {
        o[i][0] = b4.x; o[i][1] = b4.y; o[i][2] = b4.z; o[i][3] = b4.w;
    }
#pragma unroll 8
    for (int hh = 0; hh < HH; hh++) {
        float4 w4 = *(const float4*)(swo + hh * HH + h0);
#pragma unroll
        for (int i = 0; i < 4; i++) {
            float sv = S[(nq * 4 + i) * 68 + hh];
            o[i][0] = fmaf(sv, w4.x, o[i][0]);
            o[i][1] = fmaf(sv, w4.y, o[i][1]);
            o[i][2] = fmaf(sv, w4.z, o[i][2]);
            o[i][3] = fmaf(sv, w4.w, o[i][3]);
        }
    }
#pragma unroll
    for (int i = 0; i < 4; i++)
        *(float4*)(out + (size_t)(base + nq * 4 + i) * HH + h0) =
            make_float4(o[i][0], o[i][1], o[i][2], o[i][3]);
}

// ---------------- global mean pool + 2-layer head ---------------------------
__global__ __launch_bounds__(128) void head_kernel(
    const float* __restrict__ Xf, const float* __restrict__ fw1,
    const float* __restrict__ fb1, const float* __restrict__ fw2,
    const float* __restrict__ fb2, float* __restrict__ out) {
    int b = blockIdx.x;
    __shared__ float gp[2][HH];
    __shared__ float gv[HH];
    __shared__ float tv[HH];

    int h = threadIdx.x & 63;
    int half = threadIdx.x >> 6;
    float acc = 0.f;
    for (int n = half; n < NN; n += 2)
        acc += Xf[((size_t)b * NN + n) * HH + h];
    gp[half][h] = acc;
    __syncthreads();
    if (threadIdx.x < HH)
        gv[threadIdx.x] = (gp[0][threadIdx.x] + gp[1][threadIdx.x]) * (1.f / NN);
    __syncthreads();
    if (threadIdx.x < HH) {
        float a = fb1[threadIdx.x];
        for (int p = 0; p < HH; p++)
            a = fmaf(gv[p], fw1[p * HH + threadIdx.x], a);
        tv[threadIdx.x] = fmaxf(a, 0.f);
    }
    __syncthreads();
    float o = fb2[threadIdx.x];
    for (int p = 0; p < HH; p++)
        o = fmaf(tv[p], fw2[p * OUTD + threadIdx.x], o);
    out[b * OUTD + threadIdx.x] = o;
}

// ---------------- launch -----------------------------------------------------
static inline int knn_smem_bytes(int DPv) {
    int planes = (DPv == 64) ? 4 * 64 * 128 : 4 * 64 * (DPv + 8) * 2;
    return planes + 64 * 68 * 4 + 256 + 128 * 6 * 8;
}

extern "C" void kernel_launch(void* const* d_in, const int* in_sizes, int n_in,
                              void* d_out, int out_size) {
    (void)in_sizes; (void)n_in; (void)out_size;
    const float* x = (const float*)d_in[0];
    const float* w1a[3] = {(const float*)d_in[1], (const float*)d_in[5], (const float*)d_in[9]};
    const float* b1a[3] = {(const float*)d_in[2], (const float*)d_in[6], (const float*)d_in[10]};
    const float* woa[3] = {(const float*)d_in[3], (const float*)d_in[7], (const float*)d_in[11]};
    const float* boa[3] = {(const float*)d_in[4], (const float*)d_in[8], (const float*)d_in[12]};
    const float* fw1 = (const float*)d_in[13];
    const float* fb1 = (const float*)d_in[14];
    const float* fw2 = (const float*)d_in[15];
    const float* fb2 = (const float*)d_in[16];

    float *buf0, *buf1, *Ab, *Cb, *sq;
    int* nbr;
    __nv_bfloat16 *xhi, *xlo;
    cudaGetSymbolAddress((void**)&buf0, g_buf0);
    cudaGetSymbolAddress((void**)&buf1, g_buf1);
    cudaGetSymbolAddress((void**)&Ab, g_A);
    cudaGetSymbolAddress((void**)&Cb, g_C);
    cudaGetSymbolAddress((void**)&nbr, g_nbr);
    cudaGetSymbolAddress((void**)&xhi, g_xhi);
    cudaGetSymbolAddress((void**)&xlo, g_xlo);
    cudaGetSymbolAddress((void**)&sq, g_sq);

    const int smem16 = knn_smem_bytes(16);
    const int smem64 = knn_smem_bytes(64);
    const int pre3  = 3 * 3 * HH * (int)sizeof(float);
    const int pre64 = 3 * 64 * HH * (int)sizeof(float);
    cudaFuncSetAttribute(knn_mma_kernel<16>, cudaFuncAttributeMaxDynamicSharedMemorySize, smem16);
    cudaFuncSetAttribute(knn_mma_kernel<64>, cudaFuncAttributeMaxDynamicSharedMemorySize, smem64);
    cudaFuncSetAttribute(precompute_kernel<64>, cudaFuncAttributeMaxDynamicSharedMemorySize, pre64);

    const int CONV_G = BB * NN / 128;
    const dim3 kg(NN / 64, BB);
    const int PRE_G = BB * NN / 64;
    const int AGG_G = BB * NN / 64;

    // layer 0 (D = 3, padded to 16)
    convert_kernel<3, 16><<<CONV_G, 128>>>(x, xhi, xlo, sq);
    knn_mma_kernel<16><<<kg, 128, smem16>>>(xhi, xlo, sq, nbr);
    precompute_kernel<3><<<PRE_G, 256, pre3>>>(x, w1a[0], b1a[0], Ab, Cb);
    edge_agg_kernel<<<AGG_G, 256>>>(nbr, Ab, Cb, woa[0], boa[0], buf0);

    // layer 1 (D = 64)
    convert_kernel<64, 64><<<CONV_G, 128>>>(buf0, xhi, xlo, sq);
    knn_mma_kernel<64><<<kg, 128, smem64>>>(buf0 ? xhi : xhi, xlo, sq, nbr);
    precompute_kernel<64><<<PRE_G, 256, pre64>>>(buf0, w1a[1], b1a[1], Ab, Cb);
    edge_agg_kernel<<<AGG_G, 256>>>(nbr, Ab, Cb, woa[1], boa[1], buf1);

    // layer 2 (D = 64)
    convert_kernel<64, 64><<<CONV_G, 128>>>(buf1, xhi, xlo, sq);
    knn_mma_kernel<64><<<kg, 128, smem64>>>(xhi, xlo, sq, nbr);
    precompute_kernel<64><<<PRE_G, 256, pre64>>>(buf1, w1a[2], b1a[2], Ab, Cb);
    edge_agg_kernel<<<AGG_G, 256>>>(nbr, Ab, Cb, woa[2], boa[2], buf0);

    head_kernel<<<BB, 128>>>(buf0, fw1, fb1, fw2, fb2, (float*)d_out);
}

// round 8
// speedup vs baseline: 1.4154x; 1.4154x over previous
#include <cuda_runtime.h>
#include <cuda_bf16.h>
#include <cstdint>

#define BB   32
#define NN   2048
#define HH   64
#define OUTD 128
#define KK   16

// ---------------- scratch (static device globals; no runtime allocation) ----
__device__ float g_buf0[BB * NN * HH];
__device__ float g_buf1[BB * NN * HH];
__device__ float g_A[BB * NN * HH];
__device__ float g_C[BB * NN * HH];
__device__ int   g_nbr[BB * NN * KK];
__device__ __align__(16) __nv_bfloat16 g_xhi[BB * NN * HH];
__device__ __align__(16) __nv_bfloat16 g_xlo[BB * NN * HH];
__device__ float g_sq[BB * NN];

// ---------------- fp32 -> (bf16 hi, bf16 lo) split + squared norms ----------
template <int D, int DP>
__global__ __launch_bounds__(128) void convert_kernel(
    const float* __restrict__ X, __nv_bfloat16* __restrict__ Hh,
    __nv_bfloat16* __restrict__ Ll, float* __restrict__ SQ) {
    const int node = blockIdx.x * 128 + threadIdx.x;
    const float* xp = X + (size_t)node * D;
    float s = 0.f;
#pragma unroll
    for (int d = 0; d < DP; d++) {
        float v = (d < D) ? xp[d] : 0.f;
        s = fmaf(v, v, s);
        __nv_bfloat16 h = __float2bfloat16(v);
        float r = v - __bfloat162float(h);
        Hh[(size_t)node * DP + d] = h;
        Ll[(size_t)node * DP + d] = __float2bfloat16(r);
    }
    SQ[node] = s;
}

// ---------------- asm helpers ------------------------------------------------
__device__ __forceinline__ void mma_bf16(float* c, const uint32_t* a,
                                         uint32_t b0, uint32_t b1) {
    asm volatile(
        "mma.sync.aligned.m16n8k16.row.col.f32.bf16.bf16.f32 "
        "{%0,%1,%2,%3},{%4,%5,%6,%7},{%8,%9},{%0,%1,%2,%3};"
        : "+f"(c[0]), "+f"(c[1]), "+f"(c[2]), "+f"(c[3])
        : "r"(a[0]), "r"(a[1]), "r"(a[2]), "r"(a[3]), "r"(b0), "r"(b1));
}
__device__ __forceinline__ void ldsm4(uint32_t* r, uint32_t addr) {
    asm volatile("ldmatrix.sync.aligned.m8n8.x4.shared.b16 {%0,%1,%2,%3}, [%4];"
                 : "=r"(r[0]), "=r"(r[1]), "=r"(r[2]), "=r"(r[3]) : "r"(addr));
}
#define CPA16(d, s) asm volatile("cp.async.ca.shared.global [%0], [%1], 16;" :: "r"(d), "l"(s) : "memory")
#define CPCOMMIT()  asm volatile("cp.async.commit_group;" ::: "memory")
#define CPWAIT()    asm volatile("cp.async.wait_group 0;" ::: "memory")

// ---------------- tensor-core kNN (round-5 layout, 4 CTA/SM) ----------------
// 64 queries/block, 64-candidate tiles, padded-row ldsm layout (validated),
// cp.async overlap with selection.  Index-only selection buffer (depth 5) with
// per-tile forced flush => smem 57,088 B => 4 CTAs/SM at 128 regs.
template <int DP>
__global__ __launch_bounds__(128, 4) void knn_mma_kernel(
    const __nv_bfloat16* __restrict__ Xh, const __nv_bfloat16* __restrict__ Xl,
    const float* __restrict__ SQ, int* __restrict__ nbr) {
    constexpr int NK = DP / 16;
    constexpr int QS = DP + 8;      // bf16 row stride
    constexpr int CS = 68;          // key row stride (floats)
    constexpr int NT = NN / 64;     // 32 tiles
    constexpr int CH = DP / 8;      // uint4 chunks per row
    constexpr int BD = 5;           // selection buffer depth (indices only)

    extern __shared__ __align__(16) char SB[];
    __nv_bfloat16* sQh = (__nv_bfloat16*)(SB);
    __nv_bfloat16* sQl = (__nv_bfloat16*)(SB + 64 * QS * 2);
    __nv_bfloat16* sCh = (__nv_bfloat16*)(SB + 64 * QS * 4);
    __nv_bfloat16* sCl = (__nv_bfloat16*)(SB + 64 * QS * 6);
    float* sKey = (float*)(SB + 64 * QS * 8);
    float* sSqc = (float*)(SB + 64 * QS * 8 + 64 * CS * 4);
    int*   sIBuf = (int*)(SB + 64 * QS * 8 + 64 * CS * 4 + 256);

    const int b = blockIdx.y;
    const int qbase = blockIdx.x * 64;
    const int tid = threadIdx.x;
    const int lane = tid & 31;
    const int warp = tid >> 5;

    // ---- load Q tile (once) ----
    {
        const uint4* gh = (const uint4*)(Xh + ((size_t)b * NN + qbase) * DP);
        const uint4* gl = (const uint4*)(Xl + ((size_t)b * NN + qbase) * DP);
        for (int u = tid; u < 64 * CH; u += 128) {
            int r = u / CH, c = u % CH;
            *(uint4*)(sQh + r * QS + c * 8) = gh[u];
            *(uint4*)(sQl + r * QS + c * 8) = gl[u];
        }
    }

    const uint32_t sCh_s = (uint32_t)__cvta_generic_to_shared(sCh);
    const uint32_t sCl_s = (uint32_t)__cvta_generic_to_shared(sCl);
    const uint32_t sQh_s = (uint32_t)__cvta_generic_to_shared(sQh);
    const uint32_t sQl_s = (uint32_t)__cvta_generic_to_shared(sQl);

    const int lrow = (lane & 7) + ((lane >> 3) & 1) * 8;
    const int lcolk = ((lane >> 4) & 1) * 8;

    // ---- selection state ----
    float bd[16];
    int bi[16];
#pragma unroll
    for (int t = 0; t < 16; t++) { bd[t] = 3.4028235e38f; bi[t] = 0; }
    float thr = 3.4028235e38f;
    int cnt = 0;
    const int selq = tid & 63;
    const int half = tid >> 6;

    auto loadC = [&](int ct) {
        const uint4* gh = (const uint4*)(Xh + ((size_t)b * NN + ct * 64) * DP);
        const uint4* gl = (const uint4*)(Xl + ((size_t)b * NN + ct * 64) * DP);
#pragma unroll
        for (int u = tid; u < 64 * CH; u += 128) {
            int r = u / CH, c = u % CH;
            CPA16(sCh_s + (r * QS + c * 8) * 2, gh + u);
            CPA16(sCl_s + (r * QS + c * 8) * 2, gl + u);
        }
        if (tid < 64) sSqc[tid] = SQ[b * NN + ct * 64 + tid];
        CPCOMMIT();
    };

    auto mma_tile = [&]() {
        float acc[8][4];
#pragma unroll
        for (int i = 0; i < 8; i++)
#pragma unroll
            for (int j = 0; j < 4; j++) acc[i][j] = 0.f;

#pragma unroll
        for (int ks = 0; ks < NK; ks++) {
            const int kc = ks * 16 + lcolk;
            uint32_t ah[4], al[4];
            ldsm4(ah, sQh_s + ((warp * 16 + lrow) * QS + kc) * 2);
            ldsm4(al, sQl_s + ((warp * 16 + lrow) * QS + kc) * 2);
#pragma unroll
            for (int cp = 0; cp < 4; cp++) {
                uint32_t bh[4], bl[4];
                ldsm4(bh, sCh_s + ((cp * 16 + lrow) * QS + kc) * 2);
                ldsm4(bl, sCl_s + ((cp * 16 + lrow) * QS + kc) * 2);
                mma_bf16(acc[2 * cp], ah, bh[0], bh[2]);
                mma_bf16(acc[2 * cp], ah, bl[0], bl[2]);
                mma_bf16(acc[2 * cp], al, bh[0], bh[2]);
                mma_bf16(acc[2 * cp + 1], ah, bh[1], bh[3]);
                mma_bf16(acc[2 * cp + 1], ah, bl[1], bl[3]);
                mma_bf16(acc[2 * cp + 1], al, bh[1], bh[3]);
            }
        }
        const int r0 = warp * 16 + (lane >> 2);
#pragma unroll
        for (int nt = 0; nt < 8; nt++) {
            const int n0 = nt * 8 + (lane & 3) * 2;
            float2 sq2 = *(const float2*)(sSqc + n0);
            *(float2*)(sKey + r0 * CS + n0) =
                make_float2(sq2.x - 2.f * acc[nt][0], sq2.y - 2.f * acc[nt][1]);
            *(float2*)(sKey + (r0 + 8) * CS + n0) =
                make_float2(sq2.x - 2.f * acc[nt][2], sq2.y - 2.f * acc[nt][3]);
        }
    };

    // flush: entries are GLOBAL candidate indices within tile ct; key re-read
    // from sKey (valid: forced flush at end of each tile's select).
    auto flush = [&](int ct) {
        int n = cnt;
        cnt = 0;
        const float* kq = sKey + selq * CS - ct * 64;
#pragma unroll 1
        for (int i = 0; i < n; i++) {
            int id = sIBuf[tid * BD + i];
            float k = kq[id];
            if (k < bd[15]) {
                bd[15] = k; bi[15] = id;
#pragma unroll
                for (int t = 15; t > 0; t--) {
                    if (bd[t] < bd[t - 1]) {
                        float td = bd[t]; bd[t] = bd[t - 1]; bd[t - 1] = td;
                        int ti = bi[t]; bi[t] = bi[t - 1]; bi[t - 1] = ti;
                    }
                }
            }
        }
        thr = bd[15];
    };

    auto select = [&](int ct) {
        const float* kp = sKey + selq * CS + half * 32;
        const int base = ct * 64 + half * 32;
#pragma unroll 1
        for (int g = 0; g < 8; g++) {
            if (__any_sync(0xffffffffu, cnt >= 2)) flush(ct);
            float4 v = *(const float4*)(kp + g * 4);
            const int ib = base + g * 4;
            if (v.x < thr) { sIBuf[tid * BD + cnt] = ib;     cnt++; }
            if (v.y < thr) { sIBuf[tid * BD + cnt] = ib + 1; cnt++; }
            if (v.z < thr) { sIBuf[tid * BD + cnt] = ib + 2; cnt++; }
            if (v.w < thr) { sIBuf[tid * BD + cnt] = ib + 3; cnt++; }
        }
        if (__any_sync(0xffffffffu, cnt > 0)) flush(ct);  // keys die with this tile
    };

    // ---- pipeline ----
    loadC(0);
    CPWAIT();
    __syncthreads();
    mma_tile();
#pragma unroll 1
    for (int ct = 1; ct < NT; ct++) {
        __syncthreads();
        loadC(ct);
        select(ct - 1);
        CPWAIT();
        __syncthreads();
        mma_tile();
    }
    __syncthreads();
    select(NT - 1);
    __syncthreads();

    // ---- merge two halves (stable, index tie-break); overlay inside sKey ----
    float* mD = sKey;
    int* mI = (int*)((char*)sKey + 64 * 33 * 4);
    {
        const int base = selq * 33 + half * 16;
#pragma unroll
        for (int t = 0; t < 16; t++) { mD[base + t] = bd[t]; mI[base + t] = bi[t]; }
    }
    __syncthreads();
    if (tid < 64) {
        const float* dA = mD + tid * 33;
        const int* iA = mI + tid * 33;
        int ia = 0, ib2 = 16;
        int* o = nbr + ((size_t)b * NN + qbase + tid) * KK;
#pragma unroll
        for (int r = 0; r < 16; r++) {
            float da = dA[ia], db = dA[ib2];
            int xa = iA[ia], xb = iA[ib2];
            bool ta = (da < db) || (da == db && xa < xb);
            o[r] = ta ? xa : xb;
            if (ta) ia++; else ib2++;
        }
    }
}

// ---------------- precompute: register-tiled (4 nodes x 4 h per thread) -----
template <int D>
__global__ __launch_bounds__(256) void precompute_kernel(
    const float* __restrict__ X, const float* __restrict__ w1,
    const float* __restrict__ b1, float* __restrict__ A, float* __restrict__ C) {
    extern __shared__ float PS[];
    float* swd = PS;              // D*64
    float* swb = PS + D * 64;     // D*64
    float* sxt = PS + 2 * D * 64; // D*64 transposed: sxt[d*64 + n]

    const int base = blockIdx.x * 64;
    for (int t = threadIdx.x; t < D * HH; t += 256) {
        float bot = w1[D * HH + t];
        swd[t] = w1[t] - bot;
        swb[t] = bot;
    }
    for (int t = threadIdx.x; t < 64 * D; t += 256) {
        int n = t / D, d = t % D;
        sxt[d * 64 + n] = X[(size_t)base * D + t];
    }
    __syncthreads();

    const int hq = threadIdx.x & 15;
    const int nq = threadIdx.x >> 4;
    const int h0 = hq * 4;
    const float4 bias = *(const float4*)(b1 + h0);

    float a[4][4], c[4][4];
#pragma unroll
    for (int i = 0; i < 4; i++) {
        a[i][0] = bias.x; a[i][1] = bias.y; a[i][2] = bias.z; a[i][3] = bias.w;
        c[i][0] = c[i][1] = c[i][2] = c[i][3] = 0.f;
    }

#pragma unroll
    for (int d = 0; d < D; d++) {
        float4 wd4 = *(const float4*)(swd + d * 64 + h0);
        float4 wb4 = *(const float4*)(swb + d * 64 + h0);
        float4 x4 = *(const float4*)(sxt + d * 64 + nq * 4);
        const float xv[4] = {x4.x, x4.y, x4.z, x4.w};
#pragma unroll
        for (int i = 0; i < 4; i++) {
            a[i][0] = fmaf(xv[i], wd4.x, a[i][0]);
            a[i][1] = fmaf(xv[i], wd4.y, a[i][1]);
            a[i][2] = fmaf(xv[i], wd4.z, a[i][2]);
            a[i][3] = fmaf(xv[i], wd4.w, a[i][3]);
            c[i][0] = fmaf(xv[i], wb4.x, c[i][0]);
            c[i][1] = fmaf(xv[i], wb4.y, c[i][1]);
            c[i][2] = fmaf(xv[i], wb4.z, c[i][2]);
            c[i][3] = fmaf(xv[i], wb4.w, c[i][3]);
        }
    }
#pragma unroll
    for (int i = 0; i < 4; i++) {
        const size_t row = (size_t)(base + nq * 4 + i) * HH + h0;
        *(float4*)(A + row) = make_float4(a[i][0], a[i][1], a[i][2], a[i][3]);
        *(float4*)(C + row) = make_float4(c[i][0], c[i][1], c[i][2], c[i][3]);
    }
}

// ---------------- edge aggregate + output GEMM (64 nodes/block) -------------
__global__ __launch_bounds__(256) void edge_agg_kernel(
    const int* __restrict__ nbr, const float* __restrict__ A,
    const float* __restrict__ C, const float* __restrict__ wo,
    const float* __restrict__ bo, float* __restrict__ out) {
    __shared__ float swo[HH * HH];
    __shared__ float S[64 * 68];
    __shared__ int snbr[64 * KK];

    const int base = blockIdx.x * 64;
    for (int t = threadIdx.x; t < HH * HH; t += 256) swo[t] = wo[t];
    for (int t = threadIdx.x; t < 64 * KK; t += 256) snbr[t] = nbr[(size_t)base * KK + t];
    __syncthreads();

    const int hq = threadIdx.x & 15;
    const int nq = threadIdx.x >> 4;
    const int h0 = hq * 4;
    const int bofs = ((base >> 11) << 11);
    const float* Cb = C + (size_t)bofs * HH;

#pragma unroll
    for (int i = 0; i < 4; i++) {
        const int n = nq * 4 + i;
        float4 a4 = *(const float4*)(A + (size_t)(base + n) * HH + h0);
        float sx = 0.f, sy = 0.f, sz = 0.f, sw = 0.f;
#pragma unroll
        for (int k = 0; k < KK; k++) {
            int j = snbr[n * KK + k];
            float4 c4 = *(const float4*)(Cb + (size_t)j * HH + h0);
            sx += fmaxf(a4.x + c4.x, 0.f);
            sy += fmaxf(a4.y + c4.y, 0.f);
            sz += fmaxf(a4.z + c4.z, 0.f);
            sw += fmaxf(a4.w + c4.w, 0.f);
        }
        *(float4*)(S + n * 68 + h0) =
            make_float4(sx * (1.f / KK), sy * (1.f / KK), sz * (1.f / KK), sw * (1.f / KK));
    }
    __syncthreads();

    const float4 b4 = *(const float4*)(bo + h0);
    float o[4][4];
#pragma unroll
    for (int i = 0; i < 4; i++) {
        o[i][0] = b4.x; o[i][1] = b4.y; o[i][2] = b4.z; o[i][3] = b4.w;
    }
#pragma unroll 8
    for (int hh = 0; hh < HH; hh++) {
        float4 w4 = *(const float4*)(swo + hh * HH + h0);
#pragma unroll
        for (int i = 0; i < 4; i++) {
            float sv = S[(nq * 4 + i) * 68 + hh];
            o[i][0] = fmaf(sv, w4.x, o[i][0]);
            o[i][1] = fmaf(sv, w4.y, o[i][1]);
            o[i][2] = fmaf(sv, w4.z, o[i][2]);
            o[i][3] = fmaf(sv, w4.w, o[i][3]);
        }
    }
#pragma unroll
    for (int i = 0; i < 4; i++)
        *(float4*)(out + (size_t)(base + nq * 4 + i) * HH + h0) =
            make_float4(o[i][0], o[i][1], o[i][2], o[i][3]);
}

// ---------------- global mean pool + 2-layer head ---------------------------
__global__ __launch_bounds__(128) void head_kernel(
    const float* __restrict__ Xf, const float* __restrict__ fw1,
    const float* __restrict__ fb1, const float* __restrict__ fw2,
    const float* __restrict__ fb2, float* __restrict__ out) {
    int b = blockIdx.x;
    __shared__ float gp[2][HH];
    __shared__ float gv[HH];
    __shared__ float tv[HH];

    int h = threadIdx.x & 63;
    int half = threadIdx.x >> 6;
    float acc = 0.f;
    for (int n = half; n < NN; n += 2)
        acc += Xf[((size_t)b * NN + n) * HH + h];
    gp[half][h] = acc;
    __syncthreads();
    if (threadIdx.x < HH)
        gv[threadIdx.x] = (gp[0][threadIdx.x] + gp[1][threadIdx.x]) * (1.f / NN);
    __syncthreads();
    if (threadIdx.x < HH) {
        float a = fb1[threadIdx.x];
        for (int p = 0; p < HH; p++)
            a = fmaf(gv[p], fw1[p * HH + threadIdx.x], a);
        tv[threadIdx.x] = fmaxf(a, 0.f);
    }
    __syncthreads();
    float o = fb2[threadIdx.x];
    for (int p = 0; p < HH; p++)
        o = fmaf(tv[p], fw2[p * OUTD + threadIdx.x], o);
    out[b * OUTD + threadIdx.x] = o;
}

// ---------------- launch -----------------------------------------------------
static inline int knn_smem_bytes(int DPv) {
    int QSv = DPv + 8;
    return 64 * QSv * 2 * 4 + 64 * 68 * 4 + 256 + 128 * 5 * 4;
}

extern "C" void kernel_launch(void* const* d_in, const int* in_sizes, int n_in,
                              void* d_out, int out_size) {
    (void)in_sizes; (void)n_in; (void)out_size;
    const float* x = (const float*)d_in[0];
    const float* w1a[3] = {(const float*)d_in[1], (const float*)d_in[5], (const float*)d_in[9]};
    const float* b1a[3] = {(const float*)d_in[2], (const float*)d_in[6], (const float*)d_in[10]};
    const float* woa[3] = {(const float*)d_in[3], (const float*)d_in[7], (const float*)d_in[11]};
    const float* boa[3] = {(const float*)d_in[4], (const float*)d_in[8], (const float*)d_in[12]};
    const float* fw1 = (const float*)d_in[13];
    const float* fb1 = (const float*)d_in[14];
    const float* fw2 = (const float*)d_in[15];
    const float* fb2 = (const float*)d_in[16];

    float *buf0, *buf1, *Ab, *Cb, *sq;
    int* nbr;
    __nv_bfloat16 *xhi, *xlo;
    cudaGetSymbolAddress((void**)&buf0, g_buf0);
    cudaGetSymbolAddress((void**)&buf1, g_buf1);
    cudaGetSymbolAddress((void**)&Ab, g_A);
    cudaGetSymbolAddress((void**)&Cb, g_C);
    cudaGetSymbolAddress((void**)&nbr, g_nbr);
    cudaGetSymbolAddress((void**)&xhi, g_xhi);
    cudaGetSymbolAddress((void**)&xlo, g_xlo);
    cudaGetSymbolAddress((void**)&sq, g_sq);

    const int smem16 = knn_smem_bytes(16);
    const int smem64 = knn_smem_bytes(64);
    const int pre3  = 3 * 3 * HH * (int)sizeof(float);
    const int pre64 = 3 * 64 * HH * (int)sizeof(float);
    cudaFuncSetAttribute(knn_mma_kernel<16>, cudaFuncAttributeMaxDynamicSharedMemorySize, smem16);
    cudaFuncSetAttribute(knn_mma_kernel<64>, cudaFuncAttributeMaxDynamicSharedMemorySize, smem64);
    cudaFuncSetAttribute(precompute_kernel<64>, cudaFuncAttributeMaxDynamicSharedMemorySize, pre64);

    const int CONV_G = BB * NN / 128;
    const dim3 kg(NN / 64, BB);
    const int PRE_G = BB * NN / 64;
    const int AGG_G = BB * NN / 64;

    // layer 0 (D = 3, padded to 16)
    convert_kernel<3, 16><<<CONV_G, 128>>>(x, xhi, xlo, sq);
    knn_mma_kernel<16><<<kg, 128, smem16>>>(xhi, xlo, sq, nbr);
    precompute_kernel<3><<<PRE_G, 256, pre3>>>(x, w1a[0], b1a[0], Ab, Cb);
    edge_agg_kernel<<<AGG_G, 256>>>(nbr, Ab, Cb, woa[0], boa[0], buf0);

    // layer 1 (D = 64)
    convert_kernel<64, 64><<<CONV_G, 128>>>(buf0, xhi, xlo, sq);
    knn_mma_kernel<64><<<kg, 128, smem64>>>(xhi, xlo, sq, nbr);
    precompute_kernel<64><<<PRE_G, 256, pre64>>>(buf0, w1a[1], b1a[1], Ab, Cb);
    edge_agg_kernel<<<AGG_G, 256>>>(nbr, Ab, Cb, woa[1], boa[1], buf1);

    // layer 2 (D = 64)
    convert_kernel<64, 64><<<CONV_G, 128>>>(buf1, xhi, xlo, sq);
    knn_mma_kernel<64><<<kg, 128, smem64>>>(xhi, xlo, sq, nbr);
    precompute_kernel<64><<<PRE_G, 256, pre64>>>(buf1, w1a[2], b1a[2], Ab, Cb);
    edge_agg_kernel<<<AGG_G, 256>>>(nbr, Ab, Cb, woa[2], boa[2], buf0);

    head_kernel<<<BB, 128>>>(buf0, fw1, fb1, fw2, fb2, (float*)d_out);
}

// round 10
// speedup vs baseline: 1.4693x; 1.0381x over previous
#include <cuda_runtime.h>
#include <cuda_fp16.h>
#include <cstdint>

#define BB   32
#define NN   2048
#define HH   64
#define OUTD 128
#define KK   16

// ---------------- scratch (static device globals; no runtime allocation) ----
__device__ float g_buf0[BB * NN * HH];
__device__ float g_buf1[BB * NN * HH];
__device__ float g_A[BB * NN * HH];
__device__ float g_C[BB * NN * HH];
__device__ int   g_nbr[BB * NN * KK];
__device__ __align__(16) __half g_xhi[BB * NN * HH];
__device__ __align__(16) __half g_xlo[BB * NN * HH];
__device__ float g_sq[BB * NN];

// ---------------- fp32 -> (fp16 hi, fp16 lo) split + squared norms ----------
template <int D, int DP>
__global__ __launch_bounds__(128) void convert_kernel(
    const float* __restrict__ X, __half* __restrict__ Hh,
    __half* __restrict__ Ll, float* __restrict__ SQ) {
    const int node = blockIdx.x * 128 + threadIdx.x;
    const float* xp = X + (size_t)node * D;
    float s = 0.f;
#pragma unroll
    for (int d = 0; d < DP; d++) {
        float v = (d < D) ? xp[d] : 0.f;
        s = fmaf(v, v, s);
        __half h = __float2half(v);
        float r = v - __half2float(h);
        Hh[(size_t)node * DP + d] = h;
        Ll[(size_t)node * DP + d] = __float2half(r);
    }
    SQ[node] = s;
}

// ---------------- asm helpers ------------------------------------------------
__device__ __forceinline__ void mma_f16(float* c, const uint32_t* a,
                                        uint32_t b0, uint32_t b1) {
    asm volatile(
        "mma.sync.aligned.m16n8k16.row.col.f32.f16.f16.f32 "
        "{%0,%1,%2,%3},{%4,%5,%6,%7},{%8,%9},{%0,%1,%2,%3};"
        : "+f"(c[0]), "+f"(c[1]), "+f"(c[2]), "+f"(c[3])
        : "r"(a[0]), "r"(a[1]), "r"(a[2]), "r"(a[3]), "r"(b0), "r"(b1));
}
__device__ __forceinline__ void ldsm4(uint32_t* r, uint32_t addr) {
    asm volatile("ldmatrix.sync.aligned.m8n8.x4.shared.b16 {%0,%1,%2,%3}, [%4];"
                 : "=r"(r[0]), "=r"(r[1]), "=r"(r[2]), "=r"(r[3]) : "r"(addr));
}
#define CPA16(d, s) asm volatile("cp.async.ca.shared.global [%0], [%1], 16;" :: "r"(d), "l"(s) : "memory")
#define CPCOMMIT()  asm volatile("cp.async.commit_group;" ::: "memory")
#define CPWAIT()    asm volatile("cp.async.wait_group 0;" ::: "memory")

// ---------------- tensor-core kNN (fp16 2-pass, 4 CTA/SM) -------------------
// 64 queries/block, 64-candidate tiles, padded-row ldsm layout (validated),
// cp.async overlap with selection.  Q-side single fp16, C-side split fp16:
// dot = qh*(ch + cl)  => 2 passes, 64 HMMA/warp-tile.  smem 47,872 B.
template <int DP>
__global__ __launch_bounds__(128, 4) void knn_mma_kernel(
    const __half* __restrict__ Xh, const __half* __restrict__ Xl,
    const float* __restrict__ SQ, int* __restrict__ nbr) {
    constexpr int NK = DP / 16;
    constexpr int QS = DP + 8;      // fp16 row stride
    constexpr int CS = 68;          // key row stride (floats)
    constexpr int NT = NN / 64;     // 32 tiles
    constexpr int CH = DP / 8;      // uint4 chunks per row
    constexpr int BD = 5;           // selection buffer depth (indices only)
    constexpr int PB = 64 * QS * 2; // bytes per plane

    extern __shared__ __align__(16) char SB[];
    __half* sQh = (__half*)(SB);
    __half* sCh = (__half*)(SB + PB);
    __half* sCl = (__half*)(SB + 2 * PB);
    float* sKey = (float*)(SB + 3 * PB);
    float* sSqc = (float*)(SB + 3 * PB + 64 * CS * 4);
    int*   sIBuf = (int*)(SB + 3 * PB + 64 * CS * 4 + 256);

    const int b = blockIdx.y;
    const int qbase = blockIdx.x * 64;
    const int tid = threadIdx.x;
    const int lane = tid & 31;
    const int warp = tid >> 5;

    // ---- load Q tile hi plane (once) ----
    {
        const uint4* gh = (const uint4*)(Xh + ((size_t)b * NN + qbase) * DP);
        for (int u = tid; u < 64 * CH; u += 128) {
            int r = u / CH, c = u % CH;
            *(uint4*)(sQh + r * QS + c * 8) = gh[u];
        }
    }

    const uint32_t sQh_s = (uint32_t)__cvta_generic_to_shared(sQh);
    const uint32_t sCh_s = (uint32_t)__cvta_generic_to_shared(sCh);
    const uint32_t sCl_s = (uint32_t)__cvta_generic_to_shared(sCl);

    const int lrow = (lane & 7) + ((lane >> 3) & 1) * 8;
    const int lcolk = ((lane >> 4) & 1) * 8;

    // ---- selection state ----
    float bd[16];
    int bi[16];
#pragma unroll
    for (int t = 0; t < 16; t++) { bd[t] = 3.4028235e38f; bi[t] = 0; }
    float thr = 3.4028235e38f;
    int cnt = 0;
    const int selq = tid & 63;
    const int half = tid >> 6;

    auto loadC = [&](int ct) {
        const uint4* gh = (const uint4*)(Xh + ((size_t)b * NN + ct * 64) * DP);
        const uint4* gl = (const uint4*)(Xl + ((size_t)b * NN + ct * 64) * DP);
#pragma unroll
        for (int u = tid; u < 64 * CH; u += 128) {
            int r = u / CH, c = u % CH;
            CPA16(sCh_s + (r * QS + c * 8) * 2, gh + u);
            CPA16(sCl_s + (r * QS + c * 8) * 2, gl + u);
        }
        if (tid < 64) sSqc[tid] = SQ[b * NN + ct * 64 + tid];
        CPCOMMIT();
    };

    auto mma_tile = [&]() {
        float acc[8][4];
#pragma unroll
        for (int i = 0; i < 8; i++)
#pragma unroll
            for (int j = 0; j < 4; j++) acc[i][j] = 0.f;

#pragma unroll
        for (int ks = 0; ks < NK; ks++) {
            const int kc = ks * 16 + lcolk;
            uint32_t ah[4];
            ldsm4(ah, sQh_s + ((warp * 16 + lrow) * QS + kc) * 2);
#pragma unroll
            for (int cp = 0; cp < 4; cp++) {
                uint32_t bh[4], bl[4];
                ldsm4(bh, sCh_s + ((cp * 16 + lrow) * QS + kc) * 2);
                ldsm4(bl, sCl_s + ((cp * 16 + lrow) * QS + kc) * 2);
                mma_f16(acc[2 * cp], ah, bh[0], bh[2]);
                mma_f16(acc[2 * cp], ah, bl[0], bl[2]);
                mma_f16(acc[2 * cp + 1], ah, bh[1], bh[3]);
                mma_f16(acc[2 * cp + 1], ah, bl[1], bl[3]);
            }
        }
        const int r0 = warp * 16 + (lane >> 2);
#pragma unroll
        for (int nt = 0; nt < 8; nt++) {
            const int n0 = nt * 8 + (lane & 3) * 2;
            float2 sq2 = *(const float2*)(sSqc + n0);
            *(float2*)(sKey + r0 * CS + n0) =
                make_float2(sq2.x - 2.f * acc[nt][0], sq2.y - 2.f * acc[nt][1]);
            *(float2*)(sKey + (r0 + 8) * CS + n0) =
                make_float2(sq2.x - 2.f * acc[nt][2], sq2.y - 2.f * acc[nt][3]);
        }
    };

    // flush: entries are GLOBAL candidate indices within tile ct; key re-read
    // from sKey (valid: forced flush at end of each tile's select).
    auto flush = [&](int ct) {
        int n = cnt;
        cnt = 0;
        const float* kq = sKey + selq * CS - ct * 64;
#pragma unroll 1
        for (int i = 0; i < n; i++) {
            int id = sIBuf[tid * BD + i];
            float k = kq[id];
            if (k < bd[15]) {
                bd[15] = k; bi[15] = id;
#pragma unroll
                for (int t = 15; t > 0; t--) {
                    if (bd[t] < bd[t - 1]) {
                        float td = bd[t]; bd[t] = bd[t - 1]; bd[t - 1] = td;
                        int ti = bi[t]; bi[t] = bi[t - 1]; bi[t - 1] = ti;
                    }
                }
            }
        }
        thr = bd[15];
    };

    auto select = [&](int ct) {
        const float* kp = sKey + selq * CS + half * 32;
        const int base = ct * 64 + half * 32;
#pragma unroll 1
        for (int g = 0; g < 8; g++) {
            if (__any_sync(0xffffffffu, cnt >= 2)) flush(ct);
            float4 v = *(const float4*)(kp + g * 4);
            const int ib = base + g * 4;
            if (v.x < thr) { sIBuf[tid * BD + cnt] = ib;     cnt++; }
            if (v.y < thr) { sIBuf[tid * BD + cnt] = ib + 1; cnt++; }
            if (v.z < thr) { sIBuf[tid * BD + cnt] = ib + 2; cnt++; }
            if (v.w < thr) { sIBuf[tid * BD + cnt] = ib + 3; cnt++; }
        }
        if (__any_sync(0xffffffffu, cnt > 0)) flush(ct);  // keys die with this tile
    };

    // ---- pipeline ----
    loadC(0);
    CPWAIT();
    __syncthreads();
    mma_tile();
#pragma unroll 1
    for (int ct = 1; ct < NT; ct++) {
        __syncthreads();
        loadC(ct);
        select(ct - 1);
        CPWAIT();
        __syncthreads();
        mma_tile();
    }
    __syncthreads();
    select(NT - 1);
    __syncthreads();

    // ---- merge two halves (stable, index tie-break); overlay inside sKey ----
    float* mD = sKey;
    int* mI = (int*)((char*)sKey + 64 * 33 * 4);
    {
        const int base = selq * 33 + half * 16;
#pragma unroll
        for (int t = 0; t < 16; t++) { mD[base + t] = bd[t]; mI[base + t] = bi[t]; }
    }
    __syncthreads();
    if (tid < 64) {
        const float* dA = mD + tid * 33;
        const int* iA = mI + tid * 33;
        int ia = 0, ib2 = 16;
        int* o = nbr + ((size_t)b * NN + qbase + tid) * KK;
#pragma unroll
        for (int r = 0; r < 16; r++) {
            float da = dA[ia], db = dA[ib2];
            int xa = iA[ia], xb = iA[ib2];
            bool ta = (da < db) || (da == db && xa < xb);
            o[r] = ta ? xa : xb;
            if (ta) ia++; else ib2++;
        }
    }
}

// ---------------- precompute: register-tiled (4 nodes x 4 h per thread) -----
template <int D>
__global__ __launch_bounds__(256) void precompute_kernel(
    const float* __restrict__ X, const float* __restrict__ w1,
    const float* __restrict__ b1, float* __restrict__ A, float* __restrict__ C) {
    extern __shared__ float PS[];
    float* swd = PS;
    float* swb = PS + D * 64;
    float* sxt = PS + 2 * D * 64;

    const int base = blockIdx.x * 64;
    for (int t = threadIdx.x; t < D * HH; t += 256) {
        float bot = w1[D * HH + t];
        swd[t] = w1[t] - bot;
        swb[t] = bot;
    }
    for (int t = threadIdx.x; t < 64 * D; t += 256) {
        int n = t / D, d = t % D;
        sxt[d * 64 + n] = X[(size_t)base * D + t];
    }
    __syncthreads();

    const int hq = threadIdx.x & 15;
    const int nq = threadIdx.x >> 4;
    const int h0 = hq * 4;
    const float4 bias = *(const float4*)(b1 + h0);

    float a[4][4], c[4][4];
#pragma unroll
    for (int i = 0; i < 4; i++) {
        a[i][0] = bias.x; a[i][1] = bias.y; a[i][2] = bias.z; a[i][3] = bias.w;
        c[i][0] = c[i][1] = c[i][2] = c[i][3] = 0.f;
    }

#pragma unroll
    for (int d = 0; d < D; d++) {
        float4 wd4 = *(const float4*)(swd + d * 64 + h0);
        float4 wb4 = *(const float4*)(swb + d * 64 + h0);
        float4 x4 = *(const float4*)(sxt + d * 64 + nq * 4);
        const float xv[4] = {x4.x, x4.y, x4.z, x4.w};
#pragma unroll
        for (int i = 0; i < 4; i++) {
            a[i][0] = fmaf(xv[i], wd4.x, a[i][0]);
            a[i][1] = fmaf(xv[i], wd4.y, a[i][1]);
            a[i][2] = fmaf(xv[i], wd4.z, a[i][2]);
            a[i][3] = fmaf(xv[i], wd4.w, a[i][3]);
            c[i][0] = fmaf(xv[i], wb4.x, c[i][0]);
            c[i][1] = fmaf(xv[i], wb4.y, c[i][1]);
            c[i][2] = fmaf(xv[i], wb4.z, c[i][2]);
            c[i][3] = fmaf(xv[i], wb4.w, c[i][3]);
        }
    }
#pragma unroll
    for (int i = 0; i < 4; i++) {
        const size_t row = (size_t)(base + nq * 4 + i) * HH + h0;
        *(float4*)(A + row) = make_float4(a[i][0], a[i][1], a[i][2], a[i][3]);
        *(float4*)(C + row) = make_float4(c[i][0], c[i][1], c[i][2], c[i][3]);
    }
}

// ---------------- edge aggregate + output GEMM (64 nodes/block) -------------
__global__ __launch_bounds__(256) void edge_agg_kernel(
    const int* __restrict__ nbr, const float* __restrict__ A,
    const float* __restrict__ C, const float* __restrict__ wo,
    const float* __restrict__ bo, float* __restrict__ out) {
    __shared__ float swo[HH * HH];
    __shared__ float S[64 * 68];
    __shared__ int snbr[64 * KK];

    const int base = blockIdx.x * 64;
    for (int t = threadIdx.x; t < HH * HH; t += 256) swo[t] = wo[t];
    for (int t = threadIdx.x; t < 64 * KK; t += 256) snbr[t] = nbr[(size_t)base * KK + t];
    __syncthreads();

    const int hq = threadIdx.x & 15;
    const int nq = threadIdx.x >> 4;
    const int h0 = hq * 4;
    const int bofs = ((base >> 11) << 11);
    const float* Cb = C + (size_t)bofs * HH;

#pragma unroll
    for (int i = 0; i < 4; i++) {
        const int n = nq * 4 + i;
        float4 a4 = *(const float4*)(A + (size_t)(base + n) * HH + h0);
        float sx = 0.f, sy = 0.f, sz = 0.f, sw = 0.f;
#pragma unroll
        for (int k = 0; k < KK; k++) {
            int j = snbr[n * KK + k];
            float4 c4 = *(const float4*)(Cb + (size_t)j * HH + h0);
            sx += fmaxf(a4.x + c4.x, 0.f);
            sy += fmaxf(a4.y + c4.y, 0.f);
            sz += fmaxf(a4.z + c4.z, 0.f);
            sw += fmaxf(a4.w + c4.w, 0.f);
        }
        *(float4*)(S + n * 68 + h0) =
            make_float4(sx * (1.f / KK), sy * (1.f / KK), sz * (1.f / KK), sw * (1.f / KK));
    }
    __syncthreads();

    const float4 b4 = *(const float4*)(bo + h0);
    float o[4][4];
#pragma unroll
    for (int i = 0; i < 4; i++) {
        o[i][0] = b4.x; o[i][1] = b4.y; o[i][2] = b4.z; o[i][3] = b4.w;
    }
#pragma unroll 8
    for (int hh = 0; hh < HH; hh++) {
        float4 w4 = *(const float4*)(swo + hh * HH + h0);
#pragma unroll
        for (int i = 0; i < 4; i++) {
            float sv = S[(nq * 4 + i) * 68 + hh];
            o[i][0] = fmaf(sv, w4.x, o[i][0]);
            o[i][1] = fmaf(sv, w4.y, o[i][1]);
            o[i][2] = fmaf(sv, w4.z, o[i][2]);
            o[i][3] = fmaf(sv, w4.w, o[i][3]);
        }
    }
#pragma unroll
    for (int i = 0; i < 4; i++)
        *(float4*)(out + (size_t)(base + nq * 4 + i) * HH + h0) =
            make_float4(o[i][0], o[i][1], o[i][2], o[i][3]);
}

// ---------------- global mean pool + 2-layer head ---------------------------
__global__ __launch_bounds__(128) void head_kernel(
    const float* __restrict__ Xf, const float* __restrict__ fw1,
    const float* __restrict__ fb1, const float* __restrict__ fw2,
    const float* __restrict__ fb2, float* __restrict__ out) {
    int b = blockIdx.x;
    __shared__ float gp[2][HH];
    __shared__ float gv[HH];
    __shared__ float tv[HH];

    int h = threadIdx.x & 63;
    int half = threadIdx.x >> 6;
    float acc = 0.f;
    for (int n = half; n < NN; n += 2)
        acc += Xf[((size_t)b * NN + n) * HH + h];
    gp[half][h] = acc;
    __syncthreads();
    if (threadIdx.x < HH)
        gv[threadIdx.x] = (gp[0][threadIdx.x] + gp[1][threadIdx.x]) * (1.f / NN);
    __syncthreads();
    if (threadIdx.x < HH) {
        float a = fb1[threadIdx.x];
        for (int p = 0; p < HH; p++)
            a = fmaf(gv[p], fw1[p * HH + threadIdx.x], a);
        tv[threadIdx.x] = fmaxf(a, 0.f);
    }
    __syncthreads();
    float o = fb2[threadIdx.x];
    for (int p = 0; p < HH; p++)
        o = fmaf(tv[p], fw2[p * OUTD + threadIdx.x], o);
    out[b * OUTD + threadIdx.x] = o;
}

// ---------------- launch -----------------------------------------------------
static inline int knn_smem_bytes(int DPv) {
    int QSv = DPv + 8;
    return 3 * 64 * QSv * 2 + 64 * 68 * 4 + 256 + 128 * 5 * 4;
}

extern "C" void kernel_launch(void* const* d_in, const int* in_sizes, int n_in,
                              void* d_out, int out_size) {
    (void)in_sizes; (void)n_in; (void)out_size;
    const float* x = (const float*)d_in[0];
    const float* w1a[3] = {(const float*)d_in[1], (const float*)d_in[5], (const float*)d_in[9]};
    const float* b1a[3] = {(const float*)d_in[2], (const float*)d_in[6], (const float*)d_in[10]};
    const float* woa[3] = {(const float*)d_in[3], (const float*)d_in[7], (const float*)d_in[11]};
    const float* boa[3] = {(const float*)d_in[4], (const float*)d_in[8], (const float*)d_in[12]};
    const float* fw1 = (const float*)d_in[13];
    const float* fb1 = (const float*)d_in[14];
    const float* fw2 = (const float*)d_in[15];
    const float* fb2 = (const float*)d_in[16];

    float *buf0, *buf1, *Ab, *Cb, *sq;
    int* nbr;
    __half *xhi, *xlo;
    cudaGetSymbolAddress((void**)&buf0, g_buf0);
    cudaGetSymbolAddress((void**)&buf1, g_buf1);
    cudaGetSymbolAddress((void**)&Ab, g_A);
    cudaGetSymbolAddress((void**)&Cb, g_C);
    cudaGetSymbolAddress((void**)&nbr, g_nbr);
    cudaGetSymbolAddress((void**)&xhi, g_xhi);
    cudaGetSymbolAddress((void**)&xlo, g_xlo);
    cudaGetSymbolAddress((void**)&sq, g_sq);

    const int smem16 = knn_smem_bytes(16);
    const int smem64 = knn_smem_bytes(64);
    const int pre3  = 3 * 3 * HH * (int)sizeof(float);
    const int pre64 = 3 * 64 * HH * (int)sizeof(float);
    cudaFuncSetAttribute(knn_mma_kernel<16>, cudaFuncAttributeMaxDynamicSharedMemorySize, smem16);
    cudaFuncSetAttribute(knn_mma_kernel<64>, cudaFuncAttributeMaxDynamicSharedMemorySize, smem64);
    cudaFuncSetAttribute(precompute_kernel<64>, cudaFuncAttributeMaxDynamicSharedMemorySize, pre64);

    const int CONV_G = BB * NN / 128;
    const dim3 kg(NN / 64, BB);
    const int PRE_G = BB * NN / 64;
    const int AGG_G = BB * NN / 64;

    // layer 0 (D = 3, padded to 16)
    convert_kernel<3, 16><<<CONV_G, 128>>>(x, xhi, xlo, sq);
    knn_mma_kernel<16><<<kg, 128, smem16>>>(xhi, xlo, sq, nbr);
    precompute_kernel<3><<<PRE_G, 256, pre3>>>(x, w1a[0], b1a[0], Ab, Cb);
    edge_agg_kernel<<<AGG_G, 256>>>(nbr, Ab, Cb, woa[0], boa[0], buf0);

    // layer 1 (D = 64)
    convert_kernel<64, 64><<<CONV_G, 128>>>(buf0, xhi, xlo, sq);
    knn_mma_kernel<64><<<kg, 128, smem64>>>(xhi, xlo, sq, nbr);
    precompute_kernel<64><<<PRE_G, 256, pre64>>>(buf0, w1a[1], b1a[1], Ab, Cb);
    edge_agg_kernel<<<AGG_G, 256>>>(nbr, Ab, Cb, woa[1], boa[1], buf1);

    // layer 2 (D = 64)
    convert_kernel<64, 64><<<CONV_G, 128>>>(buf1, xhi, xlo, sq);
    knn_mma_kernel<64><<<kg, 128, smem64>>>(xhi, xlo, sq, nbr);
    precompute_kernel<64><<<PRE_G, 256, pre64>>>(buf1, w1a[2], b1a[2], Ab, Cb);
    edge_agg_kernel<<<AGG_G, 256>>>(nbr, Ab, Cb, woa[2], boa[2], buf0);

    head_kernel<<<BB, 128>>>(buf0, fw1, fb1, fw2, fb2, (float*)d_out);
}